// round 1
// baseline (speedup 1.0000x reference)
#include <cuda_runtime.h>
#include <cuda_bf16.h>
#include <cstdint>

// Problem constants (from reference_code)
#define N_SAMPLES  65536
#define START_SIZE 4096
#define N_EVENTS   32
#define STEP       (N_SAMPLES / START_SIZE)   // 16
#define ROW_F4     (N_SAMPLES / 4)            // 16384 float4 per row

// Scratch: per-event shift in float4 units (d = idx*16 floats -> d4 = idx*4)
__device__ int g_shift4[N_EVENTS];

// Map float bits to an order-preserving unsigned key
__device__ __forceinline__ unsigned int ord_key(float v) {
    unsigned int u = __float_as_uint(v);
    return (u & 0x80000000u) ? ~u : (u | 0x80000000u);
}

// Kernel A: per-event argmax over START_SIZE logits. First-max tie rule
// (matches jnp.argmax): combined key = (ord(val) << 32) | (0xFFFFFFFF - idx),
// so max() prefers larger value, then smaller index.
__global__ void argmax_kernel(const float* __restrict__ pos) {
    const int e = blockIdx.x;              // 0..31
    const float* p = pos + (size_t)e * START_SIZE;

    unsigned long long best = 0ull;
    for (int i = threadIdx.x; i < START_SIZE; i += blockDim.x) {
        unsigned long long k =
            ((unsigned long long)ord_key(p[i]) << 32) |
            (unsigned long long)(0xFFFFFFFFu - (unsigned int)i);
        if (k > best) best = k;
    }

    // warp reduce
    for (int off = 16; off > 0; off >>= 1) {
        unsigned long long o = __shfl_down_sync(0xFFFFFFFFu, best, off);
        if (o > best) best = o;
    }

    __shared__ unsigned long long s_best[4];   // 128 threads = 4 warps
    const int warp = threadIdx.x >> 5;
    if ((threadIdx.x & 31) == 0) s_best[warp] = best;
    __syncthreads();

    if (threadIdx.x == 0) {
        unsigned long long b = s_best[0];
        #pragma unroll
        for (int w = 1; w < 4; w++) if (s_best[w] > b) b = s_best[w];
        int idx = (int)(0xFFFFFFFFu - (unsigned int)(b & 0xFFFFFFFFu));
        g_shift4[e] = idx * (STEP / 4);        // shift in float4 units
    }
}

// Kernel B: shifted copy, float4-vectorized.
// out[r, j] = (j >= d4) ? in[r, j - d4] : 0   in float4 units.
__global__ void __launch_bounds__(256) shift_copy_kernel(
    const float4* __restrict__ in, float4* __restrict__ out) {
    const int r = blockIdx.y;                  // row = b*N_EVENTS + e
    const int e = r & (N_EVENTS - 1);
    const int d4 = g_shift4[e];
    const int j = blockIdx.x * blockDim.x + threadIdx.x;   // 0..ROW_F4-1

    const size_t base = (size_t)r * ROW_F4;
    float4 v;
    if (j >= d4) {
        v = in[base + j - d4];
    } else {
        v = make_float4(0.f, 0.f, 0.f, 0.f);
    }
    out[base + j] = v;
}

extern "C" void kernel_launch(void* const* d_in, const int* in_sizes, int n_in,
                              void* d_out, int out_size) {
    const float* events = (const float*)d_in[0];   // (B, 32, 65536) f32
    const float* pos    = (const float*)d_in[1];   // (1, 32, 4096)  f32

    const int batch = in_sizes[0] / (N_EVENTS * N_SAMPLES);   // 8
    const int rows  = batch * N_EVENTS;                       // 256

    argmax_kernel<<<N_EVENTS, 128>>>(pos);

    dim3 grid(ROW_F4 / 256, rows);
    shift_copy_kernel<<<grid, 256>>>((const float4*)events, (float4*)d_out);
}

// round 2
// speedup vs baseline: 1.0894x; 1.0894x over previous
#include <cuda_runtime.h>
#include <cuda_bf16.h>
#include <cstdint>

// Problem constants
#define N_SAMPLES   65536
#define START_SIZE  4096
#define N_EVENTS    32
#define ROW_F4      (N_SAMPLES / 4)          // 16384 float4 per row
#define SEGS_PER_ROW 8
#define SEG_F4      (ROW_F4 / SEGS_PER_ROW)  // 2048 float4 per segment
#define THREADS     256
#define F4_PER_THR  (SEG_F4 / THREADS)       // 8

// Scratch state (device globals — no allocations allowed)
__device__ int      g_shift4[N_EVENTS];  // per-event shift in float4 units
__device__ unsigned g_ready = 0;         // producers completed
__device__ unsigned g_done  = 0;         // blocks completed (for replay reset)

// Order-preserving unsigned key for float compare
__device__ __forceinline__ unsigned ord_key(float v) {
    unsigned u = __float_as_uint(v);
    return (u & 0x80000000u) ? ~u : (u | 0x80000000u);
}

__global__ void __launch_bounds__(THREADS)
fused_shift_kernel(const float4* __restrict__ in,
                   const float*  __restrict__ pos,
                   float4* __restrict__ out)
{
    const int bid = blockIdx.x;
    const int tid = threadIdx.x;

    // ---------------- Phase 1: blocks 0..31 compute argmax for event=bid ---
    if (bid < N_EVENTS) {
        const float4* p4 = (const float4*)(pos + (size_t)bid * START_SIZE);
        unsigned long long best = 0ull;
        #pragma unroll
        for (int k = 0; k < START_SIZE / 4 / THREADS; k++) {   // 4 iterations
            const int i4 = tid + k * THREADS;
            const float4 v = p4[i4];
            const int b = i4 * 4;
            unsigned long long k0 = ((unsigned long long)ord_key(v.x) << 32) | (0xFFFFFFFFu - (unsigned)(b + 0));
            unsigned long long k1 = ((unsigned long long)ord_key(v.y) << 32) | (0xFFFFFFFFu - (unsigned)(b + 1));
            unsigned long long k2 = ((unsigned long long)ord_key(v.z) << 32) | (0xFFFFFFFFu - (unsigned)(b + 2));
            unsigned long long k3 = ((unsigned long long)ord_key(v.w) << 32) | (0xFFFFFFFFu - (unsigned)(b + 3));
            if (k0 > best) best = k0;
            if (k1 > best) best = k1;
            if (k2 > best) best = k2;
            if (k3 > best) best = k3;
        }
        // warp reduce
        #pragma unroll
        for (int off = 16; off > 0; off >>= 1) {
            unsigned long long o = __shfl_down_sync(0xFFFFFFFFu, best, off);
            if (o > best) best = o;
        }
        __shared__ unsigned long long s_best[THREADS / 32];
        if ((tid & 31) == 0) s_best[tid >> 5] = best;
        __syncthreads();
        if (tid == 0) {
            unsigned long long b = s_best[0];
            #pragma unroll
            for (int w = 1; w < THREADS / 32; w++) if (s_best[w] > b) b = s_best[w];
            const int idx = (int)(0xFFFFFFFFu - (unsigned)(b & 0xFFFFFFFFu));
            g_shift4[bid] = idx * 4;                    // STEP=16 floats = 4 float4
            __threadfence();                            // publish before counter
            atomicAdd(&g_ready, 1u);
        }
    }

    // ---------------- Phase 2: wait until all 32 shifts are published ------
    if (tid == 0) {
        unsigned v;
        do {
            asm volatile("ld.acquire.gpu.global.u32 %0, [%1];"
                         : "=r"(v) : "l"(&g_ready) : "memory");
        } while (v < N_EVENTS);
    }
    __syncthreads();   // ordering for whole block behind t0's acquire

    // ---------------- Phase 3: shifted copy, 8 float4 per thread ----------
    const int row = bid >> 3;                 // bid / SEGS_PER_ROW
    const int seg = bid & (SEGS_PER_ROW - 1);
    const int e   = row & (N_EVENTS - 1);
    const int d4  = __ldcg(&g_shift4[e]);     // bypass L1 (cross-SM produced)

    const size_t rbase = (size_t)row * ROW_F4;
    const int j0 = seg * SEG_F4 + tid;

    float4 vals[F4_PER_THR];
    #pragma unroll
    for (int k = 0; k < F4_PER_THR; k++) {
        const int j   = j0 + k * THREADS;
        const int src = j - d4;
        vals[k] = (src >= 0) ? in[rbase + src]
                             : make_float4(0.f, 0.f, 0.f, 0.f);
    }
    #pragma unroll
    for (int k = 0; k < F4_PER_THR; k++) {
        out[rbase + j0 + k * THREADS] = vals[k];
    }

    // ---------------- Phase 4: last block resets flags (replay-safe) ------
    __syncthreads();
    if (tid == 0) {
        const unsigned old = atomicAdd(&g_done, 1u);
        if (old == gridDim.x - 1) {           // every block passed the spin
            atomicExch(&g_ready, 0u);
            atomicExch(&g_done,  0u);
        }
    }
}

extern "C" void kernel_launch(void* const* d_in, const int* in_sizes, int n_in,
                              void* d_out, int out_size) {
    const float* events = (const float*)d_in[0];   // (B, 32, 65536) f32
    const float* pos    = (const float*)d_in[1];   // (1, 32, 4096)  f32

    const int batch = in_sizes[0] / (N_EVENTS * N_SAMPLES);   // 8
    const int rows  = batch * N_EVENTS;                       // 256
    const int grid  = rows * SEGS_PER_ROW;                    // 2048

    fused_shift_kernel<<<grid, THREADS>>>((const float4*)events, pos,
                                          (float4*)d_out);
}